// round 3
// baseline (speedup 1.0000x reference)
#include <cuda_runtime.h>
#include <cuda_bf16.h>

// Problem constants (fixed by the dataset)
#define NNODES 100000
#define FIN    256
#define DOUT   64

// Scratch: __device__ globals (no allocation allowed)
__device__ float g_deg[NNODES];            // degree, then in-place dinv = rsqrt(deg)
__device__ float g_xw [NNODES * DOUT];     // features @ W
__device__ float g_out[NNODES * DOUT];     // aggregated output per node

// ---------------------------------------------------------------------------
// K1: init degree to 1.0 (self-loop)
__global__ void k_init_deg(int n) {
    int i = blockIdx.x * blockDim.x + threadIdx.x;
    if (i < n) g_deg[i] = 1.0f;
}

// K2: accumulate in-degree over edges (dst occurrences)
__global__ void k_edge_deg(const int* __restrict__ ei, int E) {
    int e = blockIdx.x * blockDim.x + threadIdx.x;
    if (e < E) {
        int d = ei[E + e];                 // dst row of edge_index
        atomicAdd(&g_deg[d], 1.0f);        // emitted as RED (result unused)
    }
}

// K3: dinv = rsqrt(deg) in place (deg >= 1 always due to self-loop)
__global__ void k_dinv(int n) {
    int i = blockIdx.x * blockDim.x + threadIdx.x;
    if (i < n) g_deg[i] = rsqrtf(g_deg[i]);
}

// ---------------------------------------------------------------------------
// K4: xw = F @ W   (n x 256) @ (256 x 64), and init
//     g_out[r] = xw[r] * dinv[r]^2 + b   (self-loop message + bias)
// Tile: 64 rows x 64 cols per block, BK=16, 256 threads, 4x4 microtile.
__global__ void k_gemm(const float* __restrict__ F,
                       const float* __restrict__ W,
                       const float* __restrict__ b, int n) {
    __shared__ float As[16][64];   // As[k][row]  (transposed stage)
    __shared__ float Bs[16][64];   // Bs[k][col]

    const int tid  = threadIdx.x;
    const int row0 = blockIdx.x * 64;
    const int tx   = tid & 15;     // col group 0..15  -> cols tx*4..tx*4+3
    const int ty   = tid >> 4;     // row group 0..15  -> rows ty*4..ty*4+3

    const int lr = tid >> 2;          // staging: row 0..63
    const int lk = (tid & 3) << 2;    // staging: k offset 0,4,8,12

    float acc[4][4];
#pragma unroll
    for (int i = 0; i < 4; i++)
#pragma unroll
        for (int j = 0; j < 4; j++) acc[i][j] = 0.0f;

    for (int kc = 0; kc < FIN; kc += 16) {
        // stage A (features) transposed
        float4 a = make_float4(0.f, 0.f, 0.f, 0.f);
        int gr = row0 + lr;
        if (gr < n) a = *(const float4*)&F[(size_t)gr * FIN + kc + lk];
        As[lk + 0][lr] = a.x;
        As[lk + 1][lr] = a.y;
        As[lk + 2][lr] = a.z;
        As[lk + 3][lr] = a.w;
        // stage B (W chunk): thread (ty,tx) loads W[kc+ty][tx*4..+3]
        *(float4*)&Bs[ty][tx << 2] = *(const float4*)&W[(kc + ty) * DOUT + (tx << 2)];
        __syncthreads();

#pragma unroll
        for (int k = 0; k < 16; k++) {
            float4 av = *(const float4*)&As[k][ty << 2];
            float4 bv = *(const float4*)&Bs[k][tx << 2];
            acc[0][0] += av.x * bv.x; acc[0][1] += av.x * bv.y;
            acc[0][2] += av.x * bv.z; acc[0][3] += av.x * bv.w;
            acc[1][0] += av.y * bv.x; acc[1][1] += av.y * bv.y;
            acc[1][2] += av.y * bv.z; acc[1][3] += av.y * bv.w;
            acc[2][0] += av.z * bv.x; acc[2][1] += av.z * bv.y;
            acc[2][2] += av.z * bv.z; acc[2][3] += av.z * bv.w;
            acc[3][0] += av.w * bv.x; acc[3][1] += av.w * bv.y;
            acc[3][2] += av.w * bv.z; acc[3][3] += av.w * bv.w;
        }
        __syncthreads();
    }

    // epilogue
    float4 bb = *(const float4*)&b[tx << 2];
#pragma unroll
    for (int i = 0; i < 4; i++) {
        int r = row0 + (ty << 2) + i;
        if (r < n) {
            float di = g_deg[r];          // dinv
            float s  = di * di;           // self-loop norm
            float4 v = make_float4(acc[i][0], acc[i][1], acc[i][2], acc[i][3]);
            *(float4*)&g_xw[(size_t)r * DOUT + (tx << 2)] = v;
            float4 o;
            o.x = v.x * s + bb.x;
            o.y = v.y * s + bb.y;
            o.z = v.z * s + bb.z;
            o.w = v.w * s + bb.w;
            *(float4*)&g_out[(size_t)r * DOUT + (tx << 2)] = o;
        }
    }
}

// ---------------------------------------------------------------------------
// K5: edge scatter. 16 threads per edge; each handles one float4 (4 of 64 cols).
__global__ void k_scatter(const int* __restrict__ ei, int E) {
    unsigned int t = blockIdx.x * blockDim.x + threadIdx.x;
    int e = t >> 4;
    int q = t & 15;
    if (e >= E) return;
    int s = ei[e];
    int d = ei[E + e];
    float norm = g_deg[s] * g_deg[d];
    float4 v = *(const float4*)&g_xw[(size_t)s * DOUT + (q << 2)];
    float* p = &g_out[(size_t)d * DOUT + (q << 2)];
    asm volatile("red.global.add.v4.f32 [%0], {%1,%2,%3,%4};"
                 :: "l"(p), "f"(v.x * norm), "f"(v.y * norm),
                    "f"(v.z * norm), "f"(v.w * norm)
                 : "memory");
}

// ---------------------------------------------------------------------------
// K6: gather out_full[x] -> output. 16 threads per index (float4 each).
__global__ void k_gather(const int* __restrict__ x, float* __restrict__ out, int M) {
    unsigned int t = blockIdx.x * blockDim.x + threadIdx.x;
    int s = t >> 4;
    int q = t & 15;
    if (s >= M) return;
    int node = x[s];
    *(float4*)&out[(size_t)s * DOUT + (q << 2)] =
        *(const float4*)&g_out[(size_t)node * DOUT + (q << 2)];
}

// ---------------------------------------------------------------------------
extern "C" void kernel_launch(void* const* d_in, const int* in_sizes, int n_in,
                              void* d_out, int out_size) {
    const float* features = (const float*)d_in[0];   // [N, 256]
    const int*   ei       = (const int*)  d_in[1];   // [2, E]
    const float* W        = (const float*)d_in[2];   // [256, 64]
    const float* b        = (const float*)d_in[3];   // [64]
    const int*   x        = (const int*)  d_in[4];   // [batch*fields]

    const int n = in_sizes[0] / FIN;      // 100000
    const int E = in_sizes[1] / 2;        // 3200000
    const int M = in_sizes[4];            // 81920 index entries

    const int TPB = 256;

    k_init_deg<<<(n + TPB - 1) / TPB, TPB>>>(n);
    k_edge_deg<<<(E + TPB - 1) / TPB, TPB>>>(ei, E);
    k_dinv    <<<(n + TPB - 1) / TPB, TPB>>>(n);
    k_gemm    <<<(n + 63) / 64, 256>>>(features, W, b, n);
    {
        long long tot = (long long)E * 16;
        k_scatter<<<(unsigned)((tot + 511) / 512), 512>>>(ei, E);
    }
    {
        long long tot = (long long)M * 16;
        k_gather<<<(unsigned)((tot + TPB - 1) / TPB), TPB>>>(x, (float*)d_out, M);
    }
}

// round 4
// speedup vs baseline: 1.5338x; 1.5338x over previous
#include <cuda_runtime.h>
#include <cuda_bf16.h>

#define NNODES 100000
#define FIN    256
#define DOUT   64
#define NEDGE_MAX 3200000
#define SCAN_B 512

// Scratch (__device__ globals; no allocation allowed)
__device__ int   g_cnt [NNODES];        // in-degree counts (excl. self)
__device__ int   g_flag[NNODES];        // node referenced by x?
__device__ float g_dinv[NNODES];        // rsqrt(deg)
__device__ int   g_rowstart[NNODES];    // CSR row offsets (exclusive scan)
__device__ int   g_cur[NNODES];         // fill cursors
__device__ int   g_part[256];           // scan partials (196 used)
__device__ int   g_csrc[NEDGE_MAX];     // CSR src ids
__device__ float g_xw [NNODES * DOUT];  // features @ W
__device__ float g_out[NNODES * DOUT];  // aggregated per-node output

// ---------------------------------------------------------------------------
__global__ void k_init(int n) {
    int i = blockIdx.x * blockDim.x + threadIdx.x;
    if (i < n) { g_cnt[i] = 0; g_flag[i] = 0; }
}

__global__ void k_mark(const int* __restrict__ x, int M) {
    int i = blockIdx.x * blockDim.x + threadIdx.x;
    if (i < M) g_flag[x[i]] = 1;
}

__global__ void k_count(const int* __restrict__ ei, int E) {
    int e = blockIdx.x * blockDim.x + threadIdx.x;
    if (e < E) atomicAdd(&g_cnt[ei[E + e]], 1);
}

__global__ void k_dinv(int n) {
    int i = blockIdx.x * blockDim.x + threadIdx.x;
    if (i < n) g_dinv[i] = rsqrtf((float)(g_cnt[i] + 1));
}

// --- 3-phase exclusive scan of g_cnt -> g_rowstart -------------------------
__global__ void k_scan_local(int n) {
    __shared__ int sh[SCAN_B];
    int t = threadIdx.x;
    int i = blockIdx.x * SCAN_B + t;
    int v = (i < n) ? g_cnt[i] : 0;
    sh[t] = v;
    __syncthreads();
#pragma unroll
    for (int off = 1; off < SCAN_B; off <<= 1) {
        int add = (t >= off) ? sh[t - off] : 0;
        __syncthreads();
        sh[t] += add;
        __syncthreads();
    }
    if (i < n) g_rowstart[i] = sh[t] - v;          // local exclusive
    if (t == SCAN_B - 1) g_part[blockIdx.x] = sh[t];
}

__global__ void k_scan_part(int nblk) {
    __shared__ int sh[256];
    int t = threadIdx.x;
    int v = (t < nblk) ? g_part[t] : 0;
    sh[t] = v;
    __syncthreads();
#pragma unroll
    for (int off = 1; off < 256; off <<= 1) {
        int add = (t >= off) ? sh[t - off] : 0;
        __syncthreads();
        sh[t] += add;
        __syncthreads();
    }
    if (t < nblk) g_part[t] = sh[t] - v;           // exclusive
}

__global__ void k_scan_add(int n) {
    int i = blockIdx.x * blockDim.x + threadIdx.x;
    if (i < n) {
        int v = g_rowstart[i] + g_part[i >> 9];    // 512 = 2^9
        g_rowstart[i] = v;
        g_cur[i] = v;
    }
}

// --- CSR fill (only for dst nodes that are actually read) ------------------
__global__ void k_fill(const int* __restrict__ ei, int E) {
    int e = blockIdx.x * blockDim.x + threadIdx.x;
    if (e >= E) return;
    int d = ei[E + e];
    if (g_flag[d]) {
        int pos = atomicAdd(&g_cur[d], 1);
        g_csrc[pos] = ei[e];
    }
}

// ---------------------------------------------------------------------------
// GEMM: xw = F @ W. 128x64 tile, BK=16, 256 threads, 8x4 microtile.
__global__ void k_gemm(const float* __restrict__ F,
                       const float* __restrict__ W, int n) {
    __shared__ float As[16][128];   // As[k][row]
    __shared__ float Bs[16][64];    // Bs[k][col]

    const int tid  = threadIdx.x;
    const int row0 = blockIdx.x * 128;
    const int tx   = tid & 15;      // cols tx*4..+3
    const int ty   = tid >> 4;      // rows ty*8..+7

    float acc[8][4];
#pragma unroll
    for (int i = 0; i < 8; i++)
#pragma unroll
        for (int j = 0; j < 4; j++) acc[i][j] = 0.0f;

    for (int kc = 0; kc < FIN; kc += 16) {
        // stage A transposed: 512 float4 loads, 2 per thread
#pragma unroll
        for (int i = 0; i < 2; i++) {
            int idx = tid + 256 * i;        // 0..511
            int kg  = idx >> 7;             // 0..3  -> k offset kg*4
            int r   = idx & 127;
            float4 a = make_float4(0.f, 0.f, 0.f, 0.f);
            int gr = row0 + r;
            if (gr < n) a = *(const float4*)&F[(size_t)gr * FIN + kc + (kg << 2)];
            As[(kg << 2) + 0][r] = a.x;
            As[(kg << 2) + 1][r] = a.y;
            As[(kg << 2) + 2][r] = a.z;
            As[(kg << 2) + 3][r] = a.w;
        }
        // stage B: thread (ty,tx) loads W[kc+ty][tx*4..+3]
        *(float4*)&Bs[tid >> 4][(tid & 15) << 2] =
            *(const float4*)&W[(kc + (tid >> 4)) * DOUT + ((tid & 15) << 2)];
        __syncthreads();

#pragma unroll
        for (int k = 0; k < 16; k++) {
            float4 a0 = *(const float4*)&As[k][(ty << 3)];
            float4 a1 = *(const float4*)&As[k][(ty << 3) + 4];
            float4 bv = *(const float4*)&Bs[k][tx << 2];
            float av[8] = {a0.x, a0.y, a0.z, a0.w, a1.x, a1.y, a1.z, a1.w};
#pragma unroll
            for (int i = 0; i < 8; i++) {
                acc[i][0] += av[i] * bv.x;
                acc[i][1] += av[i] * bv.y;
                acc[i][2] += av[i] * bv.z;
                acc[i][3] += av[i] * bv.w;
            }
        }
        __syncthreads();
    }

#pragma unroll
    for (int i = 0; i < 8; i++) {
        int r = row0 + (ty << 3) + i;
        if (r < n)
            *(float4*)&g_xw[(size_t)r * DOUT + (tx << 2)] =
                make_float4(acc[i][0], acc[i][1], acc[i][2], acc[i][3]);
    }
}

// ---------------------------------------------------------------------------
// Aggregate: one warp per dst node (only flagged). Lane owns 2 output floats.
__global__ void k_agg(const float* __restrict__ b, int n) {
    int w = (blockIdx.x * blockDim.x + threadIdx.x) >> 5;
    if (w >= n) return;
    if (!g_flag[w]) return;
    int lane = threadIdx.x & 31;

    float di = g_dinv[w];
    int start = g_rowstart[w];
    int end   = start + g_cnt[w];

    // self-loop term
    float2 xv = *(const float2*)&g_xw[(size_t)w * DOUT + (lane << 1)];
    float s = di * di;
    float ax = xv.x * s, ay = xv.y * s;

    int j = start;
    // unroll-by-2 for MLP
    for (; j + 2 <= end; j += 2) {
        int s0 = g_csrc[j];
        int s1 = g_csrc[j + 1];
        float n0 = g_dinv[s0] * di;
        float n1 = g_dinv[s1] * di;
        float2 v0 = *(const float2*)&g_xw[(size_t)s0 * DOUT + (lane << 1)];
        float2 v1 = *(const float2*)&g_xw[(size_t)s1 * DOUT + (lane << 1)];
        ax += v0.x * n0; ay += v0.y * n0;
        ax += v1.x * n1; ay += v1.y * n1;
    }
    if (j < end) {
        int s0 = g_csrc[j];
        float n0 = g_dinv[s0] * di;
        float2 v0 = *(const float2*)&g_xw[(size_t)s0 * DOUT + (lane << 1)];
        ax += v0.x * n0; ay += v0.y * n0;
    }

    float2 bb = *(const float2*)&b[lane << 1];
    *(float2*)&g_out[(size_t)w * DOUT + (lane << 1)] =
        make_float2(ax + bb.x, ay + bb.y);
}

// ---------------------------------------------------------------------------
__global__ void k_gather(const int* __restrict__ x, float* __restrict__ out, int M) {
    unsigned int t = blockIdx.x * blockDim.x + threadIdx.x;
    int s = t >> 4;
    int q = t & 15;
    if (s >= M) return;
    int node = x[s];
    *(float4*)&out[(size_t)s * DOUT + (q << 2)] =
        *(const float4*)&g_out[(size_t)node * DOUT + (q << 2)];
}

// ---------------------------------------------------------------------------
extern "C" void kernel_launch(void* const* d_in, const int* in_sizes, int n_in,
                              void* d_out, int out_size) {
    const float* features = (const float*)d_in[0];
    const int*   ei       = (const int*)  d_in[1];
    const float* W        = (const float*)d_in[2];
    const float* b        = (const float*)d_in[3];
    const int*   x        = (const int*)  d_in[4];

    const int n = in_sizes[0] / FIN;       // 100000
    const int E = in_sizes[1] / 2;         // 3200000
    const int M = in_sizes[4];             // 81920

    const int TPB = 256;
    const int nblk_scan = (n + SCAN_B - 1) / SCAN_B;   // 196

    k_init      <<<(n + TPB - 1) / TPB, TPB>>>(n);
    k_mark      <<<(M + TPB - 1) / TPB, TPB>>>(x, M);
    k_count     <<<(E + TPB - 1) / TPB, TPB>>>(ei, E);
    k_dinv      <<<(n + TPB - 1) / TPB, TPB>>>(n);
    k_scan_local<<<nblk_scan, SCAN_B>>>(n);
    k_scan_part <<<1, 256>>>(nblk_scan);
    k_scan_add  <<<(n + TPB - 1) / TPB, TPB>>>(n);
    k_fill      <<<(E + TPB - 1) / TPB, TPB>>>(ei, E);
    k_gemm      <<<(n + 127) / 128, 256>>>(features, W, n);
    k_agg       <<<(n * 32 + TPB - 1) / TPB, TPB>>>(b, n);
    {
        long long tot = (long long)M * 16;
        k_gather<<<(unsigned)((tot + TPB - 1) / TPB), TPB>>>(x, (float*)d_out, M);
    }
}

// round 8
// speedup vs baseline: 1.5510x; 1.0112x over previous
#include <cuda_runtime.h>
#include <cuda_bf16.h>

#define NNODES 100000
#define FIN    256
#define DOUT   64
#define NEDGE_MAX 3200000
#define SCAN_B 512

// Scratch (__device__ globals; no allocation allowed)
__device__ int   g_cnt [NNODES];        // in-degree counts (excl. self)
__device__ int   g_flag[NNODES];        // node referenced by x?
__device__ float g_dinv[NNODES];        // rsqrt(deg)
__device__ int   g_rowstart[NNODES];    // CSR row offsets (exclusive scan)
__device__ int   g_cur[NNODES];         // fill cursors
__device__ int   g_part[256];           // scan partials (196 used)
__device__ int   g_csrc[NEDGE_MAX];     // CSR src ids
__device__ float g_xw [NNODES * DOUT];  // features @ W
__device__ float g_out[NNODES * DOUT];  // aggregated per-node output

// ---- packed f32x2 helpers -------------------------------------------------
__device__ __forceinline__ void ffma2(unsigned long long& d,
                                      unsigned long long a,
                                      unsigned long long b) {
    asm("fma.rn.f32x2 %0, %1, %2, %0;" : "+l"(d) : "l"(a), "l"(b));
}
__device__ __forceinline__ unsigned long long bcast2(float v) {
    unsigned long long p;
    asm("mov.b64 %0, {%1, %1};" : "=l"(p) : "f"(v));
    return p;
}
__device__ __forceinline__ void unpack2(unsigned long long p, float& lo, float& hi) {
    asm("mov.b64 {%0, %1}, %2;" : "=f"(lo), "=f"(hi) : "l"(p));
}

// ---------------------------------------------------------------------------
// K1: zero cnt + flag (int4 vectorized; NNODES % 4 == 0)
__global__ void k_init(int n4) {
    int i = blockIdx.x * blockDim.x + threadIdx.x;
    if (i < n4) {
        ((int4*)g_cnt)[i]  = make_int4(0, 0, 0, 0);
        ((int4*)g_flag)[i] = make_int4(0, 0, 0, 0);
    }
}

// K2: mark nodes referenced by x (int4; M % 4 == 0)
__global__ void k_mark(const int* __restrict__ x, int M4) {
    int i = blockIdx.x * blockDim.x + threadIdx.x;
    if (i < M4) {
        int4 v = ((const int4*)x)[i];
        g_flag[v.x] = 1; g_flag[v.y] = 1; g_flag[v.z] = 1; g_flag[v.w] = 1;
    }
}

// K3: in-degree counts over dst (int4; E % 4 == 0)
__global__ void k_count(const int* __restrict__ dst, int E4) {
    int i = blockIdx.x * blockDim.x + threadIdx.x;
    if (i < E4) {
        int4 d = ((const int4*)dst)[i];
        atomicAdd(&g_cnt[d.x], 1);
        atomicAdd(&g_cnt[d.y], 1);
        atomicAdd(&g_cnt[d.z], 1);
        atomicAdd(&g_cnt[d.w], 1);
    }
}

// --- 3-phase exclusive scan of g_cnt -> g_rowstart -------------------------
__global__ void k_scan_local(int n) {
    __shared__ int sh[SCAN_B];
    int t = threadIdx.x;
    int i = blockIdx.x * SCAN_B + t;
    int v = (i < n) ? g_cnt[i] : 0;
    sh[t] = v;
    __syncthreads();
#pragma unroll
    for (int off = 1; off < SCAN_B; off <<= 1) {
        int add = (t >= off) ? sh[t - off] : 0;
        __syncthreads();
        sh[t] += add;
        __syncthreads();
    }
    if (i < n) g_rowstart[i] = sh[t] - v;          // local exclusive
    if (t == SCAN_B - 1) g_part[blockIdx.x] = sh[t];
}

__global__ void k_scan_part(int nblk) {
    __shared__ int sh[256];
    int t = threadIdx.x;
    int v = (t < nblk) ? g_part[t] : 0;
    sh[t] = v;
    __syncthreads();
#pragma unroll
    for (int off = 1; off < 256; off <<= 1) {
        int add = (t >= off) ? sh[t - off] : 0;
        __syncthreads();
        sh[t] += add;
        __syncthreads();
    }
    if (t < nblk) g_part[t] = sh[t] - v;           // exclusive
}

// K6: finalize offsets + cursors + dinv (fused)
__global__ void k_scan_add(int n) {
    int i = blockIdx.x * blockDim.x + threadIdx.x;
    if (i < n) {
        int v = g_rowstart[i] + g_part[i >> 9];    // SCAN_B = 2^9
        g_rowstart[i] = v;
        g_cur[i] = v;
        g_dinv[i] = rsqrtf((float)(g_cnt[i] + 1)); // +1 self-loop
    }
}

// --- CSR fill, only for flagged dst (int2 vectorized; E % 2 == 0) ----------
__global__ void k_fill(const int* __restrict__ ei, int E, int E2) {
    int i = blockIdx.x * blockDim.x + threadIdx.x;
    if (i >= E2) return;
    int2 s = ((const int2*)ei)[i];
    int2 d = ((const int2*)(ei + E))[i];
    if (g_flag[d.x]) {
        int pos = atomicAdd(&g_cur[d.x], 1);
        g_csrc[pos] = s.x;
    }
    if (g_flag[d.y]) {
        int pos = atomicAdd(&g_cur[d.y], 1);
        g_csrc[pos] = s.y;
    }
}

// ---------------------------------------------------------------------------
// GEMM: xw = F @ W. 128x64 tile, BK=16, 256 threads, 8x4 microtile,
// packed fma.rn.f32x2 (row-pairs packed; B broadcast-packed).
__global__ void k_gemm(const float* __restrict__ F,
                       const float* __restrict__ W, int n) {
    __shared__ __align__(16) float As[16][128];   // As[k][row]
    __shared__ __align__(16) float Bs[16][64];    // Bs[k][col]

    const int tid  = threadIdx.x;
    const int row0 = blockIdx.x * 128;
    const int tx   = tid & 15;      // cols tx*4..+3
    const int ty   = tid >> 4;      // rows ty*8..+7

    // acc2[rp][c]: packed pair of rows (ty*8+rp*2, +1) at col tx*4+c
    unsigned long long acc2[4][4];
#pragma unroll
    for (int i = 0; i < 4; i++)
#pragma unroll
        for (int j = 0; j < 4; j++) acc2[i][j] = 0ULL;

    for (int kc = 0; kc < FIN; kc += 16) {
        // stage A transposed: 512 float4 loads, 2 per thread
#pragma unroll
        for (int i = 0; i < 2; i++) {
            int idx = tid + 256 * i;        // 0..511
            int kg  = idx >> 7;             // 0..3  -> k offset kg*4
            int r   = idx & 127;
            float4 a = make_float4(0.f, 0.f, 0.f, 0.f);
            int gr = row0 + r;
            if (gr < n) a = *(const float4*)&F[(size_t)gr * FIN + kc + (kg << 2)];
            As[(kg << 2) + 0][r] = a.x;
            As[(kg << 2) + 1][r] = a.y;
            As[(kg << 2) + 2][r] = a.z;
            As[(kg << 2) + 3][r] = a.w;
        }
        // stage B
        *(float4*)&Bs[tid >> 4][(tid & 15) << 2] =
            *(const float4*)&W[(kc + (tid >> 4)) * DOUT + ((tid & 15) << 2)];
        __syncthreads();

#pragma unroll
        for (int k = 0; k < 16; k++) {
            // row pairs arrive pre-packed from LDS.128
            ulonglong2 a01 = *(const ulonglong2*)&As[k][ty << 3];
            ulonglong2 a23 = *(const ulonglong2*)&As[k][(ty << 3) + 4];
            float4 bv = *(const float4*)&Bs[k][tx << 2];
            unsigned long long b0 = bcast2(bv.x);
            unsigned long long b1 = bcast2(bv.y);
            unsigned long long b2 = bcast2(bv.z);
            unsigned long long b3 = bcast2(bv.w);
            ffma2(acc2[0][0], a01.x, b0); ffma2(acc2[0][1], a01.x, b1);
            ffma2(acc2[0][2], a01.x, b2); ffma2(acc2[0][3], a01.x, b3);
            ffma2(acc2[1][0], a01.y, b0); ffma2(acc2[1][1], a01.y, b1);
            ffma2(acc2[1][2], a01.y, b2); ffma2(acc2[1][3], a01.y, b3);
            ffma2(acc2[2][0], a23.x, b0); ffma2(acc2[2][1], a23.x, b1);
            ffma2(acc2[2][2], a23.x, b2); ffma2(acc2[2][3], a23.x, b3);
            ffma2(acc2[3][0], a23.y, b0); ffma2(acc2[3][1], a23.y, b1);
            ffma2(acc2[3][2], a23.y, b2); ffma2(acc2[3][3], a23.y, b3);
        }
        __syncthreads();
    }

#pragma unroll
    for (int rp = 0; rp < 4; rp++) {
        float lo0, hi0, lo1, hi1, lo2, hi2, lo3, hi3;
        unpack2(acc2[rp][0], lo0, hi0);
        unpack2(acc2[rp][1], lo1, hi1);
        unpack2(acc2[rp][2], lo2, hi2);
        unpack2(acc2[rp][3], lo3, hi3);
        int r0 = row0 + (ty << 3) + (rp << 1);
        if (r0 < n)
            *(float4*)&g_xw[(size_t)r0 * DOUT + (tx << 2)] =
                make_float4(lo0, lo1, lo2, lo3);
        if (r0 + 1 < n)
            *(float4*)&g_xw[(size_t)(r0 + 1) * DOUT + (tx << 2)] =
                make_float4(hi0, hi1, hi2, hi3);
    }
}

// ---------------------------------------------------------------------------
// Aggregate: one warp per flagged dst node. Lane owns 2 output floats.
__global__ void k_agg(const float* __restrict__ b, int n) {
    int w = (blockIdx.x * blockDim.x + threadIdx.x) >> 5;
    if (w >= n) return;
    if (!g_flag[w]) return;
    int lane = threadIdx.x & 31;

    float di = g_dinv[w];
    int start = g_rowstart[w];
    int end   = start + g_cnt[w];

    // self-loop term
    float2 xv = *(const float2*)&g_xw[(size_t)w * DOUT + (lane << 1)];
    float s = di * di;
    float ax = xv.x * s, ay = xv.y * s;

    int j = start;
    for (; j + 2 <= end; j += 2) {
        int s0 = g_csrc[j];
        int s1 = g_csrc[j + 1];
        float n0 = g_dinv[s0] * di;
        float n1 = g_dinv[s1] * di;
        float2 v0 = *(const float2*)&g_xw[(size_t)s0 * DOUT + (lane << 1)];
        float2 v1 = *(const float2*)&g_xw[(size_t)s1 * DOUT + (lane << 1)];
        ax += v0.x * n0; ay += v0.y * n0;
        ax += v1.x * n1; ay += v1.y * n1;
    }
    if (j < end) {
        int s0 = g_csrc[j];
        float n0 = g_dinv[s0] * di;
        float2 v0 = *(const float2*)&g_xw[(size_t)s0 * DOUT + (lane << 1)];
        ax += v0.x * n0; ay += v0.y * n0;
    }

    float2 bb = *(const float2*)&b[lane << 1];
    *(float2*)&g_out[(size_t)w * DOUT + (lane << 1)] =
        make_float2(ax + bb.x, ay + bb.y);
}

// ---------------------------------------------------------------------------
__global__ void k_gather(const int* __restrict__ x, float* __restrict__ out, int M) {
    unsigned int t = blockIdx.x * blockDim.x + threadIdx.x;
    int s = t >> 4;
    int q = t & 15;
    if (s >= M) return;
    int node = x[s];
    *(float4*)&out[(size_t)s * DOUT + (q << 2)] =
        *(const float4*)&g_out[(size_t)node * DOUT + (q << 2)];
}

// ---------------------------------------------------------------------------
extern "C" void kernel_launch(void* const* d_in, const int* in_sizes, int n_in,
                              void* d_out, int out_size) {
    const float* features = (const float*)d_in[0];
    const int*   ei       = (const int*)  d_in[1];
    const float* W        = (const float*)d_in[2];
    const float* b        = (const float*)d_in[3];
    const int*   x        = (const int*)  d_in[4];

    const int n = in_sizes[0] / FIN;       // 100000
    const int E = in_sizes[1] / 2;         // 3200000
    const int M = in_sizes[4];             // 81920

    const int TPB = 256;
    const int nblk_scan = (n + SCAN_B - 1) / SCAN_B;   // 196
    const int n4 = n / 4, M4 = M / 4, E4 = E / 4, E2 = E / 2;

    k_init      <<<(n4 + TPB - 1) / TPB, TPB>>>(n4);
    k_mark      <<<(M4 + TPB - 1) / TPB, TPB>>>(x, M4);
    k_count     <<<(E4 + TPB - 1) / TPB, TPB>>>(ei + E, E4);
    k_scan_local<<<nblk_scan, SCAN_B>>>(n);
    k_scan_part <<<1, 256>>>(nblk_scan);
    k_scan_add  <<<(n + TPB - 1) / TPB, TPB>>>(n);
    k_fill      <<<(E2 + TPB - 1) / TPB, TPB>>>(ei, E, E2);
    k_gemm      <<<(n + 127) / 128, 256>>>(features, W, n);
    k_agg       <<<(n * 32 + TPB - 1) / TPB, TPB>>>(b, n);
    {
        long long tot = (long long)M * 16;
        k_gather<<<(unsigned)((tot + TPB - 1) / TPB), TPB>>>(x, (float*)d_out, M);
    }
}